// round 10
// baseline (speedup 1.0000x reference)
#include <cuda_runtime.h>
#include <cuda_bf16.h>
#include <cstdint>

// DenseGridNet via warp-level mma.sync bf16 (m16n8k16), split-bf16 x3
// compensation. R10: three independent accumulator chains (hh/hl/lh) per
// n-tile to break the 12-deep dependent HMMA chain, and fused uint4 B
// fragments (one LDS.128 per mma triple instead of two LDS.64).

#define THREADS 256
#define TILE 128
#define NCTA 296
#define FS 132   // ftile row stride in floats

__device__ __forceinline__ void splitpack(float v0, float v1,
                                          uint32_t& hi, uint32_t& lo) {
    __nv_bfloat16 h0 = __float2bfloat16(v0);
    __nv_bfloat16 h1 = __float2bfloat16(v1);
    float l0 = v0 - __bfloat162float(h0);
    float l1 = v1 - __bfloat162float(h1);
    __nv_bfloat162 hp = __halves2bfloat162(h0, h1);   // .x in low 16 bits
    __nv_bfloat162 lp = __halves2bfloat162(__float2bfloat16(l0),
                                           __float2bfloat16(l1));
    __builtin_memcpy(&hi, &hp, 4);
    __builtin_memcpy(&lo, &lp, 4);
}

__device__ __forceinline__ void mma16816(float c[4], const uint32_t a[4],
                                         uint32_t b0, uint32_t b1) {
    asm volatile(
        "mma.sync.aligned.m16n8k16.row.col.f32.bf16.bf16.f32 "
        "{%0,%1,%2,%3}, {%4,%5,%6,%7}, {%8,%9}, {%0,%1,%2,%3};"
        : "+f"(c[0]), "+f"(c[1]), "+f"(c[2]), "+f"(c[3])
        : "r"(a[0]), "r"(a[1]), "r"(a[2]), "r"(a[3]), "r"(b0), "r"(b1));
}

__device__ __forceinline__ float4 bilerp_level(const float4* __restrict__ tab,
                                               int res, float u, float v) {
    float sx = u * (float)res, sy = v * (float)res;
    int x0 = (int)sx, y0 = (int)sy;           // truncation == astype(int32)
    float wx = sx - (float)x0, wy = sy - (float)y0;
    int x1 = min(x0 + 1, res), y1 = min(y0 + 1, res);
    int r0 = y0 * res, r1 = y1 * res;         // reference row stride == res
    float4 v00 = tab[r0 + x0], v10 = tab[r0 + x1];
    float4 v01 = tab[r1 + x0], v11 = tab[r1 + x1];
    float omwx = 1.0f - wx, omwy = 1.0f - wy;
    float4 o; float t, c;
    t = v00.x*omwx + v10.x*wx; c = v01.x*omwx + v11.x*wx; o.x = t*omwy + c*wy;
    t = v00.y*omwx + v10.y*wx; c = v01.y*omwx + v11.y*wx; o.y = t*omwy + c*wy;
    t = v00.z*omwx + v10.z*wx; c = v01.z*omwx + v11.z*wx; o.z = t*omwy + c*wy;
    t = v00.w*omwx + v10.w*wx; c = v01.w*omwx + v11.w*wx; o.w = t*omwy + c*wy;
    return o;
}

__global__ __launch_bounds__(THREADS, 2)
void densegrid_kernel(const float* __restrict__ x,
                      const float4* __restrict__ emb0,
                      const float4* __restrict__ emb1,
                      const float4* __restrict__ emb2,
                      const float* __restrict__ w1, const float* __restrict__ b1,
                      const float* __restrict__ w2, const float* __restrict__ b2,
                      const float* __restrict__ w3, const float* __restrict__ b3,
                      float* __restrict__ out, int n) {
    // Fused B fragments: {hi.b0, hi.b1, lo.b0, lo.b1} per lane. LDS.128.
    __shared__ uint4 B1[8 * 32];    // layer1: 8 n-tiles, 1 kstep
    __shared__ uint4 B2[32 * 32];   // layer2: 8 n-tiles x 4 ksteps
    __shared__ uint4 B3[4 * 32];    // layer3: 1 n-tile (N=8) x 4 ksteps
    __shared__ float b1s[64], b2s[64], b3s[8];
    __shared__ float xs[3 * TILE];
    __shared__ float ftile[16 * FS];   // [k][point], rows 13-15 = 0

    const int tid  = threadIdx.x;
    const int wid  = tid >> 5;
    const int lane = tid & 31;
    const int grp  = lane >> 2;
    const int t4   = lane & 3;

    // ---- one-time weight fragment staging ----
    for (int i = tid; i < 32 * 32; i += THREADS) {      // layer 2
        int ln = i & 31, gkk = i >> 5;
        int kk = gkk & 3, g = gkk >> 2;
        int tt = ln & 3, gp = ln >> 2;
        int nn = 8 * g + gp;
        int k0 = 16 * kk + 2 * tt;
        uint32_t h0, l0, h1, l1;
        splitpack(w2[(k0 + 0) * 64 + nn], w2[(k0 + 1) * 64 + nn], h0, l0);
        splitpack(w2[(k0 + 8) * 64 + nn], w2[(k0 + 9) * 64 + nn], h1, l1);
        B2[i] = make_uint4(h0, h1, l0, l1);
    }
    for (int i = tid; i < 8 * 32; i += THREADS) {       // layer 1 (K pad 13->16)
        int ln = i & 31, g = i >> 5;
        int tt = ln & 3, gp = ln >> 2;
        int nn = 8 * g + gp;
        int k0 = 2 * tt;
        float wa = w1[(k0 + 0) * 64 + nn];
        float wb = w1[(k0 + 1) * 64 + nn];
        float wc = (k0 + 8 < 13) ? w1[(k0 + 8) * 64 + nn] : 0.0f;
        float wd = (k0 + 9 < 13) ? w1[(k0 + 9) * 64 + nn] : 0.0f;
        uint32_t h0, l0, h1, l1;
        splitpack(wa, wb, h0, l0);
        splitpack(wc, wd, h1, l1);
        B1[i] = make_uint4(h0, h1, l0, l1);
    }
    for (int i = tid; i < 4 * 32; i += THREADS) {       // layer 3 (N pad 3->8)
        int ln = i & 31, kk = i >> 5;
        int tt = ln & 3, gp = ln >> 2;
        int k0 = 16 * kk + 2 * tt;
        float wa = (gp < 3) ? w3[(k0 + 0) * 3 + gp] : 0.0f;
        float wb = (gp < 3) ? w3[(k0 + 1) * 3 + gp] : 0.0f;
        float wc = (gp < 3) ? w3[(k0 + 8) * 3 + gp] : 0.0f;
        float wd = (gp < 3) ? w3[(k0 + 9) * 3 + gp] : 0.0f;
        uint32_t h0, l0, h1, l1;
        splitpack(wa, wb, h0, l0);
        splitpack(wc, wd, h1, l1);
        B3[i] = make_uint4(h0, h1, l0, l1);
    }
    for (int i = tid; i < 64; i += THREADS) { b1s[i] = b1[i]; b2s[i] = b2[i]; }
    if (tid < 8) b3s[tid] = (tid < 3) ? b3[tid] : 0.0f;
    for (int i = tid; i < 16 * FS; i += THREADS) ftile[i] = 0.0f;
    __syncthreads();

    const int n3 = n * 3;
    const int ntiles = (n + TILE - 1) / TILE;

    for (int tile = blockIdx.x; tile < ntiles; tile += gridDim.x) {
        const int base = tile * TILE;

        // ---- stage x coalesced ----
        for (int i = tid; i < 3 * TILE; i += THREADS) {
            int gi = base * 3 + i;
            xs[i] = (gi < n3) ? x[gi] : 0.0f;
        }
        __syncthreads();

        // ---- gather: threads 0-127 idf+level0 of pt p; 128-255 levels 1+2 ----
        {
            int p = tid & 127;
            float u = xs[3 * p + 1], v = xs[3 * p + 2];
            if (tid < 128) {
                ftile[0 * FS + p] = xs[3 * p];
                float4 f0 = bilerp_level(emb0, 512, u, v);
                ftile[1 * FS + p] = f0.x; ftile[2 * FS + p] = f0.y;
                ftile[3 * FS + p] = f0.z; ftile[4 * FS + p] = f0.w;
            } else {
                float4 f1 = bilerp_level(emb1, 264, u, v);
                float4 f2 = bilerp_level(emb2, 16,  u, v);
                ftile[5 * FS + p]  = f1.x; ftile[6 * FS + p]  = f1.y;
                ftile[7 * FS + p]  = f1.z; ftile[8 * FS + p]  = f1.w;
                ftile[9 * FS + p]  = f2.x; ftile[10 * FS + p] = f2.y;
                ftile[11 * FS + p] = f2.z; ftile[12 * FS + p] = f2.w;
            }
        }
        __syncthreads();

        // ---- A0 fragments (warp's 16 points, K=16) ----
        uint32_t a0h[4], a0l[4];
        {
            int p0 = 16 * wid + grp;
            int k0 = 2 * t4;
            splitpack(ftile[(k0 + 0) * FS + p0],     ftile[(k0 + 1) * FS + p0],     a0h[0], a0l[0]);
            splitpack(ftile[(k0 + 0) * FS + p0 + 8], ftile[(k0 + 1) * FS + p0 + 8], a0h[1], a0l[1]);
            splitpack(ftile[(k0 + 8) * FS + p0],     ftile[(k0 + 9) * FS + p0],     a0h[2], a0l[2]);
            splitpack(ftile[(k0 + 8) * FS + p0 + 8], ftile[(k0 + 9) * FS + p0 + 8], a0h[3], a0l[3]);
        }

        // ---- layer 1: 16 -> 64, bias+relu, split -> A1 fragments ----
        uint32_t a1h[4][4], a1l[4][4];
        #pragma unroll
        for (int g = 0; g < 8; g++) {
            float chh[4] = {0, 0, 0, 0}, chl[4] = {0, 0, 0, 0}, clh[4] = {0, 0, 0, 0};
            uint4 b = B1[g * 32 + lane];
            mma16816(chh, a0h, b.x, b.y);
            mma16816(chl, a0h, b.z, b.w);
            mma16816(clh, a0l, b.x, b.y);
            float2 bb = *(const float2*)&b1s[8 * g + 2 * t4];
            float c0 = bb.x + chh[0] + chl[0] + clh[0];
            float c1 = bb.y + chh[1] + chl[1] + clh[1];
            float c2 = bb.x + chh[2] + chl[2] + clh[2];
            float c3 = bb.y + chh[3] + chl[3] + clh[3];
            int kk = g >> 1, hf = g & 1;
            splitpack(fmaxf(c0, 0.0f), fmaxf(c1, 0.0f),
                      a1h[kk][2 * hf + 0], a1l[kk][2 * hf + 0]);
            splitpack(fmaxf(c2, 0.0f), fmaxf(c3, 0.0f),
                      a1h[kk][2 * hf + 1], a1l[kk][2 * hf + 1]);
        }

        // ---- layer 2: 64 -> 64, bias+relu, split -> A2 fragments ----
        uint32_t a2h[4][4], a2l[4][4];
        #pragma unroll
        for (int g = 0; g < 8; g++) {
            float chh[4] = {0, 0, 0, 0}, chl[4] = {0, 0, 0, 0}, clh[4] = {0, 0, 0, 0};
            #pragma unroll
            for (int kk = 0; kk < 4; kk++) {
                uint4 b = B2[(g * 4 + kk) * 32 + lane];
                mma16816(chh, a1h[kk], b.x, b.y);
                mma16816(chl, a1h[kk], b.z, b.w);
                mma16816(clh, a1l[kk], b.x, b.y);
            }
            float2 bb = *(const float2*)&b2s[8 * g + 2 * t4];
            float c0 = bb.x + chh[0] + chl[0] + clh[0];
            float c1 = bb.y + chh[1] + chl[1] + clh[1];
            float c2 = bb.x + chh[2] + chl[2] + clh[2];
            float c3 = bb.y + chh[3] + chl[3] + clh[3];
            int kk2 = g >> 1, hf = g & 1;
            splitpack(fmaxf(c0, 0.0f), fmaxf(c1, 0.0f),
                      a2h[kk2][2 * hf + 0], a2l[kk2][2 * hf + 0]);
            splitpack(fmaxf(c2, 0.0f), fmaxf(c3, 0.0f),
                      a2h[kk2][2 * hf + 1], a2l[kk2][2 * hf + 1]);
        }

        // ---- layer 3: 64 -> 8 (3 used), write output ----
        {
            float chh[4] = {0, 0, 0, 0}, chl[4] = {0, 0, 0, 0}, clh[4] = {0, 0, 0, 0};
            #pragma unroll
            for (int kk = 0; kk < 4; kk++) {
                uint4 b = B3[kk * 32 + lane];
                mma16816(chh, a2h[kk], b.x, b.y);
                mma16816(chl, a2h[kk], b.z, b.w);
                mma16816(clh, a2l[kk], b.x, b.y);
            }
            float2 bb = *(const float2*)&b3s[2 * t4];
            float c0 = bb.x + chh[0] + chl[0] + clh[0];
            float c1 = bb.y + chh[1] + chl[1] + clh[1];
            float c2 = bb.x + chh[2] + chl[2] + clh[2];
            float c3 = bb.y + chh[3] + chl[3] + clh[3];
            int p0 = base + 16 * wid + grp;
            int col = 2 * t4;
            if (col < 3) {
                if (p0 < n)     out[p0 * 3 + col]       = c0;
                if (p0 + 8 < n) out[(p0 + 8) * 3 + col] = c2;
            }
            if (col + 1 < 3) {
                if (p0 < n)     out[p0 * 3 + col + 1]       = c1;
                if (p0 + 8 < n) out[(p0 + 8) * 3 + col + 1] = c3;
            }
        }
        // next tile's ftile writes are fenced by the sync after xs staging
    }
}

extern "C" void kernel_launch(void* const* d_in, const int* in_sizes, int n_in,
                              void* d_out, int out_size) {
    const float* x    = (const float*)d_in[0];
    const float4* e0  = (const float4*)d_in[1];
    const float4* e1  = (const float4*)d_in[2];
    const float4* e2  = (const float4*)d_in[3];
    const float* w1   = (const float*)d_in[4];
    const float* b1   = (const float*)d_in[5];
    const float* w2   = (const float*)d_in[6];
    const float* b2   = (const float*)d_in[7];
    const float* w3   = (const float*)d_in[8];
    const float* b3   = (const float*)d_in[9];
    float* out        = (float*)d_out;
    int n = in_sizes[0] / 3;
    (void)n_in; (void)out_size;
    densegrid_kernel<<<NCTA, THREADS>>>(
        x, e0, e1, e2, w1, b1, w2, b2, w3, b3, out, n);
}

// round 11
// speedup vs baseline: 1.0194x; 1.0194x over previous
#include <cuda_runtime.h>
#include <cuda_bf16.h>
#include <cstdint>

// DenseGridNet via warp-level mma.sync bf16 (m16n8k16), split-bf16 x3.
// R11: cp.async software pipeline — raw grid texels for tile i+1 are staged
// into smem during tile i's MMA compute; x coords prefetched 2 tiles ahead.
// Single-chain accumulators (R9) + fused uint4 B fragments (R10).

#define THREADS 256
#define TILE 128
#define NCTA 296
#define FS 132      // ftile row stride (floats)
#define GQ 13       // staged quads per point (12 used + 1 pad, de-conflicts LDS)

struct __align__(16) Smem {
    uint4 B1[8 * 32];        // layer1 fused hi/lo B frags
    uint4 B2[32 * 32];       // layer2
    uint4 B3[4 * 32];        // layer3
    float b1s[64], b2s[64], b3s[8];
    float xs[2][3 * TILE];   // double-buffered x coords
    float ftile[16 * FS];    // [k][point]; rows 13-15 stay 0
    float4 G[TILE * GQ];     // staged raw texels: 12 float4 per point
};
#define SMEM_BYTES ((int)sizeof(Smem))

__device__ __forceinline__ uint32_t smaddr(const void* p) {
    uint32_t a;
    asm("{ .reg .u64 t; cvta.to.shared.u64 t, %1; cvt.u32.u64 %0, t; }"
        : "=r"(a) : "l"(p));
    return a;
}
#define CPA16(sm, gm) \
    asm volatile("cp.async.ca.shared.global [%0], [%1], 16;" \
                 :: "r"(sm), "l"(gm) : "memory")
#define CPA_COMMIT() asm volatile("cp.async.commit_group;" ::: "memory")
#define CPA_WAIT_ALL() asm volatile("cp.async.wait_group 0;" ::: "memory")

__device__ __forceinline__ void splitpack(float v0, float v1,
                                          uint32_t& hi, uint32_t& lo) {
    __nv_bfloat16 h0 = __float2bfloat16(v0);
    __nv_bfloat16 h1 = __float2bfloat16(v1);
    float l0 = v0 - __bfloat162float(h0);
    float l1 = v1 - __bfloat162float(h1);
    __nv_bfloat162 hp = __halves2bfloat162(h0, h1);
    __nv_bfloat162 lp = __halves2bfloat162(__float2bfloat16(l0),
                                           __float2bfloat16(l1));
    __builtin_memcpy(&hi, &hp, 4);
    __builtin_memcpy(&lo, &lp, 4);
}

__device__ __forceinline__ void mma16816(float c[4], const uint32_t a[4],
                                         uint32_t b0, uint32_t b1) {
    asm volatile(
        "mma.sync.aligned.m16n8k16.row.col.f32.bf16.bf16.f32 "
        "{%0,%1,%2,%3}, {%4,%5,%6,%7}, {%8,%9}, {%0,%1,%2,%3};"
        : "+f"(c[0]), "+f"(c[1]), "+f"(c[2]), "+f"(c[3])
        : "r"(a[0]), "r"(a[1]), "r"(a[2]), "r"(a[3]), "r"(b0), "r"(b1));
}

// gmem addresses of the 4 bilerp texels (indices clamped; identity in-range)
__device__ __forceinline__ void lvl_addrs(const float4* __restrict__ tab,
                                          int res, float u, float v,
                                          const float4*& p00, const float4*& p10,
                                          const float4*& p01, const float4*& p11) {
    float sx = u * (float)res, sy = v * (float)res;
    int x0 = max(0, min((int)sx, res));
    int y0 = max(0, min((int)sy, res));
    int x1 = min(x0 + 1, res), y1 = min(y0 + 1, res);
    int r0 = y0 * res, r1 = y1 * res;     // reference row stride == res
    p00 = tab + r0 + x0; p10 = tab + r0 + x1;
    p01 = tab + r1 + x0; p11 = tab + r1 + x1;
}

// combine staged texels with reference-exact arithmetic
__device__ __forceinline__ float4 blend(float4 v00, float4 v10, float4 v01,
                                        float4 v11, int res, float u, float v) {
    float sx = u * (float)res, sy = v * (float)res;
    int x0 = (int)sx, y0 = (int)sy;
    float wx = sx - (float)x0, wy = sy - (float)y0;
    float omwx = 1.0f - wx, omwy = 1.0f - wy;
    float4 o; float t, c;
    t = v00.x*omwx + v10.x*wx; c = v01.x*omwx + v11.x*wx; o.x = t*omwy + c*wy;
    t = v00.y*omwx + v10.y*wx; c = v01.y*omwx + v11.y*wx; o.y = t*omwy + c*wy;
    t = v00.z*omwx + v10.z*wx; c = v01.z*omwx + v11.z*wx; o.z = t*omwy + c*wy;
    t = v00.w*omwx + v10.w*wx; c = v01.w*omwx + v11.w*wx; o.w = t*omwy + c*wy;
    return o;
}

__global__ __launch_bounds__(THREADS, 2)
void densegrid_kernel(const float* __restrict__ x,
                      const float4* __restrict__ emb0,
                      const float4* __restrict__ emb1,
                      const float4* __restrict__ emb2,
                      const float* __restrict__ w1, const float* __restrict__ b1,
                      const float* __restrict__ w2, const float* __restrict__ b2,
                      const float* __restrict__ w3, const float* __restrict__ b3,
                      float* __restrict__ out, int n) {
    extern __shared__ char smraw[];
    Smem& s = *reinterpret_cast<Smem*>(smraw);

    const int tid  = threadIdx.x;
    const int wid  = tid >> 5;
    const int lane = tid & 31;
    const int grp  = lane >> 2;
    const int t4   = lane & 3;

    // ---- one-time weight fragment staging ----
    for (int i = tid; i < 32 * 32; i += THREADS) {
        int ln = i & 31, gkk = i >> 5;
        int kk = gkk & 3, g = gkk >> 2;
        int tt = ln & 3, gp = ln >> 2;
        int nn = 8 * g + gp, k0 = 16 * kk + 2 * tt;
        uint32_t h0, l0, h1, l1;
        splitpack(w2[(k0 + 0) * 64 + nn], w2[(k0 + 1) * 64 + nn], h0, l0);
        splitpack(w2[(k0 + 8) * 64 + nn], w2[(k0 + 9) * 64 + nn], h1, l1);
        s.B2[i] = make_uint4(h0, h1, l0, l1);
    }
    for (int i = tid; i < 8 * 32; i += THREADS) {
        int ln = i & 31, g = i >> 5;
        int tt = ln & 3, gp = ln >> 2;
        int nn = 8 * g + gp, k0 = 2 * tt;
        float wa = w1[(k0 + 0) * 64 + nn];
        float wb = w1[(k0 + 1) * 64 + nn];
        float wc = (k0 + 8 < 13) ? w1[(k0 + 8) * 64 + nn] : 0.0f;
        float wd = (k0 + 9 < 13) ? w1[(k0 + 9) * 64 + nn] : 0.0f;
        uint32_t h0, l0, h1, l1;
        splitpack(wa, wb, h0, l0);
        splitpack(wc, wd, h1, l1);
        s.B1[i] = make_uint4(h0, h1, l0, l1);
    }
    for (int i = tid; i < 4 * 32; i += THREADS) {
        int ln = i & 31, kk = i >> 5;
        int tt = ln & 3, gp = ln >> 2;
        int k0 = 16 * kk + 2 * tt;
        float wa = (gp < 3) ? w3[(k0 + 0) * 3 + gp] : 0.0f;
        float wb = (gp < 3) ? w3[(k0 + 1) * 3 + gp] : 0.0f;
        float wc = (gp < 3) ? w3[(k0 + 8) * 3 + gp] : 0.0f;
        float wd = (gp < 3) ? w3[(k0 + 9) * 3 + gp] : 0.0f;
        uint32_t h0, l0, h1, l1;
        splitpack(wa, wb, h0, l0);
        splitpack(wc, wd, h1, l1);
        s.B3[i] = make_uint4(h0, h1, l0, l1);
    }
    for (int i = tid; i < 64; i += THREADS) { s.b1s[i] = b1[i]; s.b2s[i] = b2[i]; }
    if (tid < 8) s.b3s[tid] = (tid < 3) ? b3[tid] : 0.0f;
    for (int i = tid; i < 16 * FS; i += THREADS) s.ftile[i] = 0.0f;

    const int n3 = n * 3;
    const int ntiles = (n + TILE - 1) / TILE;
    const int stride = gridDim.x;

    // ---- prologue: prefetch x(tile0) -> xs[0], x(tile1) -> xs[1] ----
    {
        int t0 = blockIdx.x, t1 = blockIdx.x + stride;
        if (tid < 96) {
            long gi = (long)t0 * TILE * 3 + tid * 4;
            if (gi + 3 < n3) CPA16(smaddr(&s.xs[0][tid * 4]), x + gi);
        } else if (tid < 192 && t1 < ntiles) {
            int t = tid - 96;
            long gi = (long)t1 * TILE * 3 + t * 4;
            if (gi + 3 < n3) CPA16(smaddr(&s.xs[1][t * 4]), x + gi);
        }
        CPA_COMMIT();
    }
    CPA_WAIT_ALL();
    __syncthreads();
    // ---- prologue: stage gathers for tile0 from xs[0] ----
    {
        int p = tid >> 1, h = tid & 1;
        float u = s.xs[0][3 * p + 1], v = s.xs[0][3 * p + 2];
        uint32_t gb = smaddr(&s.G[p * GQ]);
        const float4 *a, *b, *c, *d;
        if (h == 0) {
            lvl_addrs(emb0, 512, u, v, a, b, c, d);
            CPA16(gb +  0, a); CPA16(gb + 16, b);
            CPA16(gb + 32, c); CPA16(gb + 48, d);
            lvl_addrs(emb1, 264, u, v, a, b, c, d);
            CPA16(gb + 64, a); CPA16(gb + 80, b);
        } else {
            lvl_addrs(emb1, 264, u, v, a, b, c, d);
            CPA16(gb +  96, c); CPA16(gb + 112, d);
            lvl_addrs(emb2, 16, u, v, a, b, c, d);
            CPA16(gb + 128, a); CPA16(gb + 144, b);
            CPA16(gb + 160, c); CPA16(gb + 176, d);
        }
        CPA_COMMIT();
    }

    int it = 0;
    for (int tile = blockIdx.x; tile < ntiles; tile += stride, it++) {
        const int base = tile * TILE;
        const int cur = it & 1, nxt = cur ^ 1;

        CPA_WAIT_ALL();
        __syncthreads();

        // ---- bilerp from staged texels -> ftile ----
        {
            int p = tid & 127;
            const float* xv = s.xs[cur];
            float u = xv[3 * p + 1], v = xv[3 * p + 2];
            const float4* g = &s.G[p * GQ];
            if (tid < 128) {
                s.ftile[0 * FS + p] = xv[3 * p];
                float4 f0 = blend(g[0], g[1], g[2], g[3], 512, u, v);
                s.ftile[1 * FS + p] = f0.x; s.ftile[2 * FS + p] = f0.y;
                s.ftile[3 * FS + p] = f0.z; s.ftile[4 * FS + p] = f0.w;
            } else {
                float4 f1 = blend(g[4], g[5], g[6], g[7], 264, u, v);
                float4 f2 = blend(g[8], g[9], g[10], g[11], 16, u, v);
                s.ftile[5 * FS + p]  = f1.x; s.ftile[6 * FS + p]  = f1.y;
                s.ftile[7 * FS + p]  = f1.z; s.ftile[8 * FS + p]  = f1.w;
                s.ftile[9 * FS + p]  = f2.x; s.ftile[10 * FS + p] = f2.y;
                s.ftile[11 * FS + p] = f2.z; s.ftile[12 * FS + p] = f2.w;
            }
        }
        __syncthreads();

        // ---- issue prefetch for tile+stride (gathers) and tile+2*stride (x) ----
        {
            int tn = tile + stride;
            if (tn < ntiles) {
                int p = tid >> 1, h = tid & 1;
                const float* xv = s.xs[nxt];
                float u = xv[3 * p + 1], v = xv[3 * p + 2];
                uint32_t gb = smaddr(&s.G[p * GQ]);
                const float4 *a, *b, *c, *d;
                if (h == 0) {
                    lvl_addrs(emb0, 512, u, v, a, b, c, d);
                    CPA16(gb +  0, a); CPA16(gb + 16, b);
                    CPA16(gb + 32, c); CPA16(gb + 48, d);
                    lvl_addrs(emb1, 264, u, v, a, b, c, d);
                    CPA16(gb + 64, a); CPA16(gb + 80, b);
                } else {
                    lvl_addrs(emb1, 264, u, v, a, b, c, d);
                    CPA16(gb +  96, c); CPA16(gb + 112, d);
                    lvl_addrs(emb2, 16, u, v, a, b, c, d);
                    CPA16(gb + 128, a); CPA16(gb + 144, b);
                    CPA16(gb + 160, c); CPA16(gb + 176, d);
                }
            }
            int tnn = tile + 2 * stride;
            if (tid < 96 && tnn < ntiles) {
                long gi = (long)tnn * TILE * 3 + tid * 4;
                if (gi + 3 < n3) CPA16(smaddr(&s.xs[cur][tid * 4]), x + gi);
            }
            CPA_COMMIT();
        }

        // ---- A0 fragments (warp's 16 points, K=16) ----
        uint32_t a0h[4], a0l[4];
        {
            int p0 = 16 * wid + grp;
            int k0 = 2 * t4;
            splitpack(s.ftile[(k0 + 0) * FS + p0],     s.ftile[(k0 + 1) * FS + p0],     a0h[0], a0l[0]);
            splitpack(s.ftile[(k0 + 0) * FS + p0 + 8], s.ftile[(k0 + 1) * FS + p0 + 8], a0h[1], a0l[1]);
            splitpack(s.ftile[(k0 + 8) * FS + p0],     s.ftile[(k0 + 9) * FS + p0],     a0h[2], a0l[2]);
            splitpack(s.ftile[(k0 + 8) * FS + p0 + 8], s.ftile[(k0 + 9) * FS + p0 + 8], a0h[3], a0l[3]);
        }

        // ---- layer 1: 16 -> 64, bias+relu -> A1 fragments ----
        uint32_t a1h[4][4], a1l[4][4];
        #pragma unroll
        for (int g = 0; g < 8; g++) {
            float c[4];
            float2 bb = *(const float2*)&s.b1s[8 * g + 2 * t4];
            c[0] = bb.x; c[1] = bb.y; c[2] = bb.x; c[3] = bb.y;
            uint4 b = s.B1[g * 32 + lane];
            mma16816(c, a0h, b.x, b.y);
            mma16816(c, a0h, b.z, b.w);
            mma16816(c, a0l, b.x, b.y);
            int kk = g >> 1, hf = g & 1;
            splitpack(fmaxf(c[0], 0.0f), fmaxf(c[1], 0.0f),
                      a1h[kk][2 * hf + 0], a1l[kk][2 * hf + 0]);
            splitpack(fmaxf(c[2], 0.0f), fmaxf(c[3], 0.0f),
                      a1h[kk][2 * hf + 1], a1l[kk][2 * hf + 1]);
        }

        // ---- layer 2: 64 -> 64, bias+relu -> A2 fragments ----
        uint32_t a2h[4][4], a2l[4][4];
        #pragma unroll
        for (int g = 0; g < 8; g++) {
            float c[4];
            float2 bb = *(const float2*)&s.b2s[8 * g + 2 * t4];
            c[0] = bb.x; c[1] = bb.y; c[2] = bb.x; c[3] = bb.y;
            #pragma unroll
            for (int kk = 0; kk < 4; kk++) {
                uint4 b = s.B2[(g * 4 + kk) * 32 + lane];
                mma16816(c, a1h[kk], b.x, b.y);
                mma16816(c, a1h[kk], b.z, b.w);
                mma16816(c, a1l[kk], b.x, b.y);
            }
            int kk2 = g >> 1, hf = g & 1;
            splitpack(fmaxf(c[0], 0.0f), fmaxf(c[1], 0.0f),
                      a2h[kk2][2 * hf + 0], a2l[kk2][2 * hf + 0]);
            splitpack(fmaxf(c[2], 0.0f), fmaxf(c[3], 0.0f),
                      a2h[kk2][2 * hf + 1], a2l[kk2][2 * hf + 1]);
        }

        // ---- layer 3: 64 -> 8 (3 used), write output ----
        {
            float c[4];
            float2 bb = *(const float2*)&s.b3s[2 * t4];
            c[0] = bb.x; c[1] = bb.y; c[2] = bb.x; c[3] = bb.y;
            #pragma unroll
            for (int kk = 0; kk < 4; kk++) {
                uint4 b = s.B3[kk * 32 + lane];
                mma16816(c, a2h[kk], b.x, b.y);
                mma16816(c, a2h[kk], b.z, b.w);
                mma16816(c, a2l[kk], b.x, b.y);
            }
            int p0 = base + 16 * wid + grp;
            int col = 2 * t4;
            if (col < 3) {
                if (p0 < n)     out[p0 * 3 + col]       = c[0];
                if (p0 + 8 < n) out[(p0 + 8) * 3 + col] = c[2];
            }
            if (col + 1 < 3) {
                if (p0 < n)     out[p0 * 3 + col + 1]       = c[1];
                if (p0 + 8 < n) out[(p0 + 8) * 3 + col + 1] = c[3];
            }
        }
    }
}

extern "C" void kernel_launch(void* const* d_in, const int* in_sizes, int n_in,
                              void* d_out, int out_size) {
    const float* x    = (const float*)d_in[0];
    const float4* e0  = (const float4*)d_in[1];
    const float4* e1  = (const float4*)d_in[2];
    const float4* e2  = (const float4*)d_in[3];
    const float* w1   = (const float*)d_in[4];
    const float* b1   = (const float*)d_in[5];
    const float* w2   = (const float*)d_in[6];
    const float* b2   = (const float*)d_in[7];
    const float* w3   = (const float*)d_in[8];
    const float* b3   = (const float*)d_in[9];
    float* out        = (float*)d_out;
    int n = in_sizes[0] / 3;
    (void)n_in; (void)out_size;
    cudaFuncSetAttribute(densegrid_kernel,
                         cudaFuncAttributeMaxDynamicSharedMemorySize, SMEM_BYTES);
    densegrid_kernel<<<NCTA, THREADS, SMEM_BYTES>>>(
        x, e0, e1, e2, w1, b1, w2, b2, w3, b3, out, n);
}

// round 12
// speedup vs baseline: 1.1940x; 1.1713x over previous
#include <cuda_runtime.h>
#include <cuda_bf16.h>
#include <cstdint>

// DenseGridNet via warp-level mma.sync bf16 (m16n8k16), split-bf16 x3.
// R12: fast splitpack (cvt.rn.bf16x2.f32 + shift/mask residuals), gather
// phase writes A0 pre-split in fragment layout, layer-1 bias as constant-1
// K-row, launch_bounds(256,3) to target 24 warps/SM.

#define THREADS 256
#define TILE 128
#define NCTA 444
#define AS 136    // A0 row stride in words: 8*t4 bank phase -> conflict-free

__device__ __forceinline__ void splitpack(float v0, float v1,
                                          uint32_t& hi, uint32_t& lo) {
    asm("cvt.rn.bf16x2.f32 %0, %1, %2;" : "=r"(hi) : "f"(v1), "f"(v0));
    float r0 = __uint_as_float(hi << 16);          // bf16(v0) as f32
    float r1 = __uint_as_float(hi & 0xFFFF0000u);  // bf16(v1) as f32
    asm("cvt.rn.bf16x2.f32 %0, %1, %2;" : "=r"(lo) : "f"(v1 - r1), "f"(v0 - r0));
}
__device__ __forceinline__ void splitval(float v, uint32_t pos16,
                                         uint32_t& hi, uint32_t& lo) {
    // scalar helper for weight staging (pos16: 0 = low half)
    __nv_bfloat16 h = __float2bfloat16(v);
    float r = v - __bfloat162float(h);
    __nv_bfloat16 l = __float2bfloat16(r);
    uint16_t hb, lb;
    __builtin_memcpy(&hb, &h, 2);
    __builtin_memcpy(&lb, &l, 2);
    hi |= (uint32_t)hb << pos16;
    lo |= (uint32_t)lb << pos16;
}

__device__ __forceinline__ void mma16816(float c[4], const uint32_t a[4],
                                         uint32_t b0, uint32_t b1) {
    asm volatile(
        "mma.sync.aligned.m16n8k16.row.col.f32.bf16.bf16.f32 "
        "{%0,%1,%2,%3}, {%4,%5,%6,%7}, {%8,%9}, {%0,%1,%2,%3};"
        : "+f"(c[0]), "+f"(c[1]), "+f"(c[2]), "+f"(c[3])
        : "r"(a[0]), "r"(a[1]), "r"(a[2]), "r"(a[3]), "r"(b0), "r"(b1));
}

__device__ __forceinline__ float4 bilerp_level(const float4* __restrict__ tab,
                                               int res, float u, float v) {
    float sx = u * (float)res, sy = v * (float)res;
    int x0 = (int)sx, y0 = (int)sy;           // truncation == astype(int32)
    float wx = sx - (float)x0, wy = sy - (float)y0;
    int x1 = min(x0 + 1, res), y1 = min(y0 + 1, res);
    int r0 = y0 * res, r1 = y1 * res;         // reference row stride == res
    float4 v00 = tab[r0 + x0], v10 = tab[r0 + x1];
    float4 v01 = tab[r1 + x0], v11 = tab[r1 + x1];
    float omwx = 1.0f - wx, omwy = 1.0f - wy;
    float4 o; float t, c;
    t = v00.x*omwx + v10.x*wx; c = v01.x*omwx + v11.x*wx; o.x = t*omwy + c*wy;
    t = v00.y*omwx + v10.y*wx; c = v01.y*omwx + v11.y*wx; o.y = t*omwy + c*wy;
    t = v00.z*omwx + v10.z*wx; c = v01.z*omwx + v11.z*wx; o.z = t*omwy + c*wy;
    t = v00.w*omwx + v10.w*wx; c = v01.w*omwx + v11.w*wx; o.w = t*omwy + c*wy;
    return o;
}

// layer-1 weight with permuted K: k<5 -> w1 rows 0-4 (idf,f0), k==5 pad0,
// k 6-13 -> w1 rows 5-12 (f1,f2), k==14 -> bias row (A supplies 1.0), k==15 pad0.
__device__ __forceinline__ float w1val(const float* w1, const float* b1,
                                       int k, int nn) {
    if (k < 5)  return w1[k * 64 + nn];
    if (k == 5 || k == 15) return 0.0f;
    if (k <= 13) return w1[(k - 1) * 64 + nn];
    return b1[nn];   // k == 14
}

__global__ __launch_bounds__(THREADS, 3)
void densegrid_kernel(const float* __restrict__ x,
                      const float4* __restrict__ emb0,
                      const float4* __restrict__ emb1,
                      const float4* __restrict__ emb2,
                      const float* __restrict__ w1, const float* __restrict__ b1,
                      const float* __restrict__ w2, const float* __restrict__ b2,
                      const float* __restrict__ w3, const float* __restrict__ b3,
                      float* __restrict__ out, int n) {
    __shared__ uint4 B1[8 * 32];        // layer1 fused hi/lo B frags (bias row folded)
    __shared__ uint4 B2[32 * 32];       // layer2
    __shared__ uint4 B3[4 * 32];        // layer3
    __shared__ float b2s[64], b3s[8];
    __shared__ uint32_t A0h[8 * AS];    // pre-split input frags [kpair][point]
    __shared__ uint32_t A0l[8 * AS];

    const int tid  = threadIdx.x;
    const int wid  = tid >> 5;
    const int lane = tid & 31;
    const int grp  = lane >> 2;
    const int t4   = lane & 3;

    // ---- one-time weight fragment staging ----
    for (int i = tid; i < 32 * 32; i += THREADS) {      // layer 2
        int ln = i & 31, gkk = i >> 5;
        int kk = gkk & 3, g = gkk >> 2;
        int tt = ln & 3, gp = ln >> 2;
        int nn = 8 * g + gp, k0 = 16 * kk + 2 * tt;
        uint32_t h0 = 0, l0 = 0, h1 = 0, l1 = 0;
        splitval(w2[(k0 + 0) * 64 + nn], 0,  h0, l0);
        splitval(w2[(k0 + 1) * 64 + nn], 16, h0, l0);
        splitval(w2[(k0 + 8) * 64 + nn], 0,  h1, l1);
        splitval(w2[(k0 + 9) * 64 + nn], 16, h1, l1);
        B2[i] = make_uint4(h0, h1, l0, l1);
    }
    for (int i = tid; i < 8 * 32; i += THREADS) {       // layer 1 (permuted K)
        int ln = i & 31, g = i >> 5;
        int tt = ln & 3, gp = ln >> 2;
        int nn = 8 * g + gp, k0 = 2 * tt;
        uint32_t h0 = 0, l0 = 0, h1 = 0, l1 = 0;
        splitval(w1val(w1, b1, k0 + 0, nn), 0,  h0, l0);
        splitval(w1val(w1, b1, k0 + 1, nn), 16, h0, l0);
        splitval(w1val(w1, b1, k0 + 8, nn), 0,  h1, l1);
        splitval(w1val(w1, b1, k0 + 9, nn), 16, h1, l1);
        B1[i] = make_uint4(h0, h1, l0, l1);
    }
    for (int i = tid; i < 4 * 32; i += THREADS) {       // layer 3 (N pad 3->8)
        int ln = i & 31, kk = i >> 5;
        int tt = ln & 3, gp = ln >> 2;
        int k0 = 16 * kk + 2 * tt;
        uint32_t h0 = 0, l0 = 0, h1 = 0, l1 = 0;
        if (gp < 3) {
            splitval(w3[(k0 + 0) * 3 + gp], 0,  h0, l0);
            splitval(w3[(k0 + 1) * 3 + gp], 16, h0, l0);
            splitval(w3[(k0 + 8) * 3 + gp], 0,  h1, l1);
            splitval(w3[(k0 + 9) * 3 + gp], 16, h1, l1);
        }
        B3[i] = make_uint4(h0, h1, l0, l1);
    }
    for (int i = tid; i < 64; i += THREADS) b2s[i] = b2[i];
    if (tid < 8) b3s[tid] = (tid < 3) ? b3[tid] : 0.0f;
    // constant rows: kpair 7 = (1.0, 0) for the bias row (persists across tiles)
    if (tid < TILE) {
        A0h[7 * AS + tid] = 0x00003F80u;   // bf16(1.0) in low half
        A0l[7 * AS + tid] = 0u;
    }

    const int ntiles = (n + TILE - 1) / TILE;

    for (int tile = blockIdx.x; tile < ntiles; tile += gridDim.x) {
        const int base = tile * TILE;
        __syncthreads();   // previous tile's A0 reads complete before overwrite

        // ---- gather + pre-split into A0 fragments ----
        {
            int p = tid & 127;
            int idx = base + p;
            if (idx >= n) idx = n - 1;
            float u = x[idx * 3 + 1], v = x[idx * 3 + 2];
            uint32_t h, l;
            if (tid < 128) {
                float idf = x[idx * 3 + 0];
                float4 f0 = bilerp_level(emb0, 512, u, v);
                splitpack(idf, f0.x, h, l);  A0h[0 * AS + p] = h; A0l[0 * AS + p] = l;
                splitpack(f0.y, f0.z, h, l); A0h[1 * AS + p] = h; A0l[1 * AS + p] = l;
                splitpack(f0.w, 0.0f, h, l); A0h[2 * AS + p] = h; A0l[2 * AS + p] = l;
            } else {
                float4 f1 = bilerp_level(emb1, 264, u, v);
                float4 f2 = bilerp_level(emb2, 16,  u, v);
                splitpack(f1.x, f1.y, h, l); A0h[3 * AS + p] = h; A0l[3 * AS + p] = l;
                splitpack(f1.z, f1.w, h, l); A0h[4 * AS + p] = h; A0l[4 * AS + p] = l;
                splitpack(f2.x, f2.y, h, l); A0h[5 * AS + p] = h; A0l[5 * AS + p] = l;
                splitpack(f2.z, f2.w, h, l); A0h[6 * AS + p] = h; A0l[6 * AS + p] = l;
            }
        }
        __syncthreads();

        // ---- A0 fragments: direct conflict-free LDS.32 ----
        uint32_t a0h[4], a0l[4];
        {
            int pl = 16 * wid + grp;
            a0h[0] = A0h[t4 * AS + pl];       a0l[0] = A0l[t4 * AS + pl];
            a0h[1] = A0h[t4 * AS + pl + 8];   a0l[1] = A0l[t4 * AS + pl + 8];
            a0h[2] = A0h[(t4 + 4) * AS + pl];     a0l[2] = A0l[(t4 + 4) * AS + pl];
            a0h[3] = A0h[(t4 + 4) * AS + pl + 8]; a0l[3] = A0l[(t4 + 4) * AS + pl + 8];
        }

        // ---- layer 1: 16 -> 64 (bias in k=14 row), relu -> A1 frags ----
        uint32_t a1h[4][4], a1l[4][4];
        #pragma unroll
        for (int g = 0; g < 8; g++) {
            float c[4] = {0.0f, 0.0f, 0.0f, 0.0f};
            uint4 b = B1[g * 32 + lane];
            mma16816(c, a0h, b.x, b.y);
            mma16816(c, a0h, b.z, b.w);
            mma16816(c, a0l, b.x, b.y);
            int kk = g >> 1, hf = g & 1;
            splitpack(fmaxf(c[0], 0.0f), fmaxf(c[1], 0.0f),
                      a1h[kk][2 * hf + 0], a1l[kk][2 * hf + 0]);
            splitpack(fmaxf(c[2], 0.0f), fmaxf(c[3], 0.0f),
                      a1h[kk][2 * hf + 1], a1l[kk][2 * hf + 1]);
        }

        // ---- layer 2: 64 -> 64, bias+relu -> A2 frags ----
        uint32_t a2h[4][4], a2l[4][4];
        #pragma unroll
        for (int g = 0; g < 8; g++) {
            float c[4];
            float2 bb = *(const float2*)&b2s[8 * g + 2 * t4];
            c[0] = bb.x; c[1] = bb.y; c[2] = bb.x; c[3] = bb.y;
            #pragma unroll
            for (int kk = 0; kk < 4; kk++) {
                uint4 b = B2[(g * 4 + kk) * 32 + lane];
                mma16816(c, a1h[kk], b.x, b.y);
                mma16816(c, a1h[kk], b.z, b.w);
                mma16816(c, a1l[kk], b.x, b.y);
            }
            int kk2 = g >> 1, hf = g & 1;
            splitpack(fmaxf(c[0], 0.0f), fmaxf(c[1], 0.0f),
                      a2h[kk2][2 * hf + 0], a2l[kk2][2 * hf + 0]);
            splitpack(fmaxf(c[2], 0.0f), fmaxf(c[3], 0.0f),
                      a2h[kk2][2 * hf + 1], a2l[kk2][2 * hf + 1]);
        }

        // ---- layer 3: 64 -> 8 (3 used), write output ----
        {
            float c[4];
            float2 bb = *(const float2*)&b3s[2 * t4];
            c[0] = bb.x; c[1] = bb.y; c[2] = bb.x; c[3] = bb.y;
            #pragma unroll
            for (int kk = 0; kk < 4; kk++) {
                uint4 b = B3[kk * 32 + lane];
                mma16816(c, a2h[kk], b.x, b.y);
                mma16816(c, a2h[kk], b.z, b.w);
                mma16816(c, a2l[kk], b.x, b.y);
            }
            int p0 = base + 16 * wid + grp;
            int col = 2 * t4;
            if (col < 3) {
                if (p0 < n)     out[p0 * 3 + col]       = c[0];
                if (p0 + 8 < n) out[(p0 + 8) * 3 + col] = c[2];
            }
            if (col + 1 < 3) {
                if (p0 < n)     out[p0 * 3 + col + 1]       = c[1];
                if (p0 + 8 < n) out[(p0 + 8) * 3 + col + 1] = c[3];
            }
        }
    }
}

extern "C" void kernel_launch(void* const* d_in, const int* in_sizes, int n_in,
                              void* d_out, int out_size) {
    const float* x    = (const float*)d_in[0];
    const float4* e0  = (const float4*)d_in[1];
    const float4* e1  = (const float4*)d_in[2];
    const float4* e2  = (const float4*)d_in[3];
    const float* w1   = (const float*)d_in[4];
    const float* b1   = (const float*)d_in[5];
    const float* w2   = (const float*)d_in[6];
    const float* b2   = (const float*)d_in[7];
    const float* w3   = (const float*)d_in[8];
    const float* b3   = (const float*)d_in[9];
    float* out        = (float*)d_out;
    int n = in_sizes[0] / 3;
    (void)n_in; (void)out_size;
    densegrid_kernel<<<NCTA, THREADS>>>(
        x, e0, e1, e2, w1, b1, w2, b2, w3, b3, out, n);
}